// round 1
// baseline (speedup 1.0000x reference)
#include <cuda_runtime.h>

// MPS classifier: logits[b] = unit(v_b @ prod_n M_n(b)) @ C^T + log||prod||
// M_n(b) = A_n + t * D_n,  t = x[b, n+1],  D_n = B_n - A_n (10x10)
// Pair-fused: M_{2j} @ M_{2j+1} = P00 + t1*P10 + t2*P01 + t1*t2*P11
// with P-matrices batch-independent (precomputed per call).

#define NSITE 783
#define NPAIR 392      // 391 real pairs + 1 identity-padded
#define NORM_EVERY 4   // normalize every 4 pair-steps (8 sites)

// Scratch: 392 * 100 * float4 = 627 KB (static __device__ — allowed)
__device__ float4 g_pmat[NPAIR * 100];

// ---------------------------------------------------------------------------
// Precompute pair matrices. One block per pair, 128 threads (100 active).
// cores_mid layout: [n][l][f][h] -> ((l*2 + f)*10 + h), n in [0,783)
// ---------------------------------------------------------------------------
__global__ void prep_pairs_kernel(const float* __restrict__ cm) {
    __shared__ float s1[200];
    __shared__ float s2[200];
    int j = blockIdx.x;
    int t = threadIdx.x;
    int s1i = 2 * j;
    int s2i = 2 * j + 1;
    if (t < 100) {
        const float* p1 = cm + s1i * 200;
        s1[t]       = p1[t];
        s1[t + 100] = p1[t + 100];
        if (s2i < NSITE) {
            const float* p2 = cm + s2i * 200;
            s2[t]       = p2[t];
            s2[t + 100] = p2[t + 100];
        } else {
            // pad with identity: A2 = I, B2 = I  (so D2 = 0)
            #pragma unroll
            for (int q = t; q < 200; q += 100) {
                int l = q / 20;
                int h = q % 10;
                s2[q] = (l == h) ? 1.0f : 0.0f;   // same value for f=0 and f=1
            }
        }
    }
    __syncthreads();
    if (t >= 100) return;
    int l = t / 10;
    int h = t % 10;
    float p00 = 0.f, p10 = 0.f, p01 = 0.f, p11 = 0.f;
    #pragma unroll
    for (int k = 0; k < 10; k++) {
        float a1 = s1[l * 20 + k];
        float d1 = s1[l * 20 + 10 + k] - a1;   // D1 = B1 - A1
        float a2 = s2[k * 20 + h];
        float d2 = s2[k * 20 + 10 + h] - a2;   // D2 = B2 - A2
        p00 = fmaf(a1, a2, p00);
        p10 = fmaf(d1, a2, p10);
        p01 = fmaf(a1, d2, p01);
        p11 = fmaf(d1, d2, p11);
    }
    g_pmat[j * 100 + t] = make_float4(p00, p10, p01, p11);
}

// ---------------------------------------------------------------------------
// Main chain kernel. 2 batches per warp: lanes [0,16) = batch 2w, lanes
// [16,32) = batch 2w+1. Lane h (h<10) owns component h of the running row
// vector v. Width-16 shuffles broadcast v_l. Lanes h in [10,16) mirror
// lane 9 (same loads/broadcasts), masked out of reductions and stores.
// ---------------------------------------------------------------------------
__global__ void __launch_bounds__(256, 1) mps_chain_kernel(
    const float* __restrict__ x,      // [2048, 784]
    const float* __restrict__ core0,  // [1, 2, 10]
    const float* __restrict__ cls,    // [10, 10]
    float* __restrict__ out)          // [2048, 10]
{
    const unsigned FULL = 0xffffffffu;
    int lane = threadIdx.x & 31;
    int gw   = (blockIdx.x * blockDim.x + threadIdx.x) >> 5;  // 0..1023
    int half = lane >> 4;
    int h    = lane & 15;
    int hc   = (h < 10) ? h : 9;
    bool act = (h < 10);
    int b    = gw * 2 + half;
    const float* xr = x + b * 784;

    // head: v[h] = core0[0,h] + t0*(core0[1,h] - core0[0,h])
    float t0 = __ldg(xr);
    float c0a = __ldg(core0 + hc);
    float c0b = __ldg(core0 + 10 + hc);
    float v = fmaf(t0, c0b - c0a, c0a);
    float lognorm = 0.0f;

    const float4* pbase = g_pmat + hc;

    for (int j = 0; j < NPAIR; j += NORM_EVERY) {
        #pragma unroll
        for (int jj = 0; jj < NORM_EVERY; jj++) {
            int s = j + jj;
            float t1 = __ldg(xr + 2 * s + 1);
            int i2 = 2 * s + 2;
            if (i2 > 783) i2 = 783;         // identity pair ignores t2 anyway
            float t2 = __ldg(xr + i2);
            float c12 = t1 * t2;
            const float4* p = pbase + s * 100;
            float w0 = 0.0f, w1 = 0.0f;     // two accumulator chains (ILP)
            #pragma unroll
            for (int l = 0; l < 10; l += 2) {
                float vl0 = __shfl_sync(FULL, v, l, 16);
                float vl1 = __shfl_sync(FULL, v, l + 1, 16);
                float4 r0 = __ldg(p + l * 10);
                float4 r1 = __ldg(p + (l + 1) * 10);
                float m0 = fmaf(t1, r0.y, r0.x);
                m0 = fmaf(t2, r0.z, m0);
                m0 = fmaf(c12, r0.w, m0);
                w0 = fmaf(vl0, m0, w0);
                float m1 = fmaf(t1, r1.y, r1.x);
                m1 = fmaf(t2, r1.z, m1);
                m1 = fmaf(c12, r1.w, m1);
                w1 = fmaf(vl1, m1, w1);
            }
            v = w0 + w1;
        }
        // normalize + accumulate log (per half-warp, width-16 butterfly)
        float ss = act ? v * v : 0.0f;
        ss += __shfl_xor_sync(FULL, ss, 1, 16);
        ss += __shfl_xor_sync(FULL, ss, 2, 16);
        ss += __shfl_xor_sync(FULL, ss, 4, 16);
        ss += __shfl_xor_sync(FULL, ss, 8, 16);
        float nrm = fmaxf(sqrtf(ss), 1e-12f);
        lognorm += __logf(nrm);
        v *= (1.0f / nrm);
    }

    // epilogue: lane index h acts as class index o
    // logits[b,o] = sum_l v_l * cls[o,l] + lognorm
    float acc = lognorm;
    #pragma unroll
    for (int l = 0; l < 10; l++) {
        float vl = __shfl_sync(FULL, v, l, 16);
        acc = fmaf(vl, __ldg(cls + hc * 10 + l), acc);
    }
    if (act) out[b * 10 + h] = acc;
}

// ---------------------------------------------------------------------------
extern "C" void kernel_launch(void* const* d_in, const int* in_sizes, int n_in,
                              void* d_out, int out_size) {
    const float* x     = (const float*)d_in[0];  // [2048, 784]
    const float* core0 = (const float*)d_in[1];  // [1, 2, 10]
    const float* cm    = (const float*)d_in[2];  // [783, 10, 2, 10]
    const float* cls   = (const float*)d_in[3];  // [10, 10]
    float* out = (float*)d_out;                  // [2048, 10]

    prep_pairs_kernel<<<NPAIR, 128>>>(cm);
    mps_chain_kernel<<<128, 256>>>(x, core0, cls, out);
}

// round 3
// speedup vs baseline: 1.2023x; 1.2023x over previous
#include <cuda_runtime.h>
#include <cstdint>

// MPS classifier: logits[b] = unit(v_b @ prod_n M_n(b)) @ C^T + log||prod||
// M_n(b) = A_n + t*D_n, t = x[b,n+1]. Pair-fused:
// M_{2j}M_{2j+1} = P00 + t1*P10 + t2*P01 + t1t2*P11 (P batch-independent).
// Chain kernel: smem-staged double-buffered pmat (cp.async), 2 batches/warp,
// power-of-2 rescale checkpoints, single sqrt/log at the end.

#define NSITE 783
#define NPAIR 392
#define CHUNK 8
#define NCHUNK 49            // 392 / 8
#define BPB 14               // batches per block
#define THREADS 224          // 7 warps
#define NBLOCK 148

__device__ float4 g_pmat[NPAIR * 100];

__device__ __forceinline__ void cpasync16(void* dst_smem, const void* src) {
    uint32_t d = (uint32_t)__cvta_generic_to_shared(dst_smem);
    asm volatile("cp.async.cg.shared.global [%0], [%1], 16;" :: "r"(d), "l"(src) : "memory");
}

// ---------------------------------------------------------------------------
// Precompute pair matrices. One block per pair, 128 threads (100 active).
// cores_mid layout: [n][l][f][h] -> ((l*2+f)*10 + h), n in [0,783)
// ---------------------------------------------------------------------------
__global__ void prep_pairs_kernel(const float* __restrict__ cm) {
    __shared__ float s1[200];
    __shared__ float s2[200];
    int j = blockIdx.x;
    int t = threadIdx.x;
    int s2i = 2 * j + 1;
    if (t < 100) {
        const float* p1 = cm + (2 * j) * 200;
        s1[t]       = p1[t];
        s1[t + 100] = p1[t + 100];
        if (s2i < NSITE) {
            const float* p2 = cm + s2i * 200;
            s2[t]       = p2[t];
            s2[t + 100] = p2[t + 100];
        } else {
            #pragma unroll
            for (int q = t; q < 200; q += 100) {
                int l = q / 20;
                int h = q % 10;
                s2[q] = (l == h) ? 1.0f : 0.0f;   // identity pad (D2 = 0)
            }
        }
    }
    __syncthreads();
    if (t >= 100) return;
    int l = t / 10;
    int h = t % 10;
    float p00 = 0.f, p10 = 0.f, p01 = 0.f, p11 = 0.f;
    #pragma unroll
    for (int k = 0; k < 10; k++) {
        float a1 = s1[l * 20 + k];
        float d1 = s1[l * 20 + 10 + k] - a1;
        float a2 = s2[k * 20 + h];
        float d2 = s2[k * 20 + 10 + h] - a2;
        p00 = fmaf(a1, a2, p00);
        p10 = fmaf(d1, a2, p10);
        p01 = fmaf(a1, d2, p01);
        p11 = fmaf(d1, d2, p11);
    }
    g_pmat[j * 100 + t] = make_float4(p00, p10, p01, p11);
}

// ---------------------------------------------------------------------------
// Main chain kernel.
// Block: 224 threads = 7 warps = 14 batches (2 per warp, lanes [0,16)/[16,32)).
// Lane h (h<10) owns component h of the running row vector v; lanes 10-15
// mirror lane 9. pmat + x t-values staged into smem double buffers.
// ---------------------------------------------------------------------------
__global__ void __launch_bounds__(THREADS, 1) mps_chain_kernel(
    const float* __restrict__ x,      // [2048, 784]
    const float* __restrict__ core0,  // [1, 2, 10]
    const float* __restrict__ cls,    // [10, 10]
    float* __restrict__ out)          // [2048, 10]
{
    __shared__ float4 bufP[2][CHUNK * 100];   // 2 x 12.8 KB
    __shared__ float4 bufX[2][BPB * 5];       // 2 x 1.12 KB  (20 floats/batch)

    const unsigned FULL = 0xffffffffu;
    int tid  = threadIdx.x;
    int lane = tid & 31;
    int warp = tid >> 5;              // 0..6
    int half = lane >> 4;
    int h    = lane & 15;
    int hc   = (h < 10) ? h : 9;
    bool act = (h < 10);
    int wbat = warp * 2 + half;       // 0..13
    int b    = blockIdx.x * BPB + wbat;
    int bsafe = (b < 2048) ? b : 0;

    // chunk loader: 800 pmat float4 + 5(4) x-float4 per batch
    auto issue_chunk = [&](int c) {
        int pb = c & 1;
        int nvec = (c == NCHUNK - 1) ? 4 : 5;      // last chunk: don't read past row
        const float4* psrc = g_pmat + c * (CHUNK * 100);
        for (int i = tid; i < CHUNK * 100 + BPB * 5; i += THREADS) {
            if (i < CHUNK * 100) {
                cpasync16(&bufP[pb][i], psrc + i);
            } else {
                int q  = i - CHUNK * 100;
                int bi = q / 5, vv = q - bi * 5;
                if (vv < nvec) {
                    int bb = blockIdx.x * BPB + bi;
                    if (bb >= 2048) bb = 0;
                    cpasync16(&bufX[pb][bi * 5 + vv],
                              x + (size_t)bb * 784 + c * 16 + vv * 4);
                }
            }
        }
        asm volatile("cp.async.commit_group;" ::: "memory");
    };

    // head: v[h] = core0[0,h] + t0*(core0[1,h]-core0[0,h])
    float t0  = __ldg(x + (size_t)bsafe * 784);
    float c0a = __ldg(core0 + hc);
    float c0b = __ldg(core0 + 10 + hc);
    float v = fmaf(t0, c0b - c0a, c0a);
    int K = 0;                         // accumulated power-of-2 exponent

    issue_chunk(0);
    asm volatile("cp.async.wait_group 0;" ::: "memory");
    __syncthreads();

    for (int c = 0; c < NCHUNK; c++) {
        int pb = c & 1;
        if (c + 1 < NCHUNK) issue_chunk(c + 1);

        const float4* P  = bufP[pb];
        const float*  tx = (const float*)(&bufX[pb][wbat * 5]);

        #pragma unroll 4
        for (int jj = 0; jj < CHUNK; jj++) {
            // NOTE: for the identity-padded pair (last pair of last chunk),
            // tx[16] reads a stale-but-finite slot; it multiplies p01=p11=0.
            float t1  = tx[2 * jj + 1];
            float t2  = tx[2 * jj + 2];
            float c12 = t1 * t2;
            const float4* p = P + jj * 100 + hc;
            float w0 = 0.0f, w1 = 0.0f;
            #pragma unroll
            for (int l = 0; l < 10; l += 2) {
                float vl0 = __shfl_sync(FULL, v, l, 16);
                float vl1 = __shfl_sync(FULL, v, l + 1, 16);
                float4 r0 = p[l * 10];
                float4 r1 = p[(l + 1) * 10];
                float m0 = fmaf(t1, r0.y, r0.x);
                m0 = fmaf(t2, r0.z, m0);
                m0 = fmaf(c12, r0.w, m0);
                w0 = fmaf(vl0, m0, w0);
                float m1 = fmaf(t1, r1.y, r1.x);
                m1 = fmaf(t2, r1.z, m1);
                m1 = fmaf(c12, r1.w, m1);
                w1 = fmaf(vl1, m1, w1);
            }
            v = w0 + w1;
        }

        // exact power-of-2 rescale (no sqrt/log on the hot path)
        float ss = act ? v * v : 0.0f;
        ss += __shfl_xor_sync(FULL, ss, 1, 16);
        ss += __shfl_xor_sync(FULL, ss, 2, 16);
        ss += __shfl_xor_sync(FULL, ss, 4, 16);
        ss += __shfl_xor_sync(FULL, ss, 8, 16);
        int e  = (__float_as_int(ss) >> 23) & 0xff;
        int sh = (e - 127) >> 1;
        K += sh;
        v *= __int_as_float((127 - sh) << 23);

        if (c + 1 < NCHUNK)
            asm volatile("cp.async.wait_group 0;" ::: "memory");
        __syncthreads();
    }

    // final norm + single log
    float ss = act ? v * v : 0.0f;
    ss += __shfl_xor_sync(FULL, ss, 1, 16);
    ss += __shfl_xor_sync(FULL, ss, 2, 16);
    ss += __shfl_xor_sync(FULL, ss, 4, 16);
    ss += __shfl_xor_sync(FULL, ss, 8, 16);
    float nrm = fmaxf(sqrtf(ss), 1e-30f);
    float lognorm = (float)K * 0.69314718055994531f + __logf(nrm);
    v *= (1.0f / nrm);

    // logits[b,o] = sum_l v_l * cls[o,l] + lognorm   (lane h = class o)
    float acc = lognorm;
    #pragma unroll
    for (int l = 0; l < 10; l++) {
        float vl = __shfl_sync(FULL, v, l, 16);
        acc = fmaf(vl, __ldg(cls + hc * 10 + l), acc);
    }
    if (act && b < 2048) out[(size_t)b * 10 + h] = acc;
}

// ---------------------------------------------------------------------------
extern "C" void kernel_launch(void* const* d_in, const int* in_sizes, int n_in,
                              void* d_out, int out_size) {
    const float* x     = (const float*)d_in[0];  // [2048, 784]
    const float* core0 = (const float*)d_in[1];  // [1, 2, 10]
    const float* cm    = (const float*)d_in[2];  // [783, 10, 2, 10]
    const float* cls   = (const float*)d_in[3];  // [10, 10]
    float* out = (float*)d_out;                  // [2048, 10]

    prep_pairs_kernel<<<NPAIR, 128>>>(cm);
    mps_chain_kernel<<<NBLOCK, THREADS>>>(x, core0, cls, out);
}

// round 4
// speedup vs baseline: 1.4886x; 1.2381x over previous
#include <cuda_runtime.h>
#include <cstdint>

// MPS classifier: logits[b] = unit(v_b @ prod_n M_n(b)) @ C^T + log||prod||
// Pair-fused matrices P (batch-independent) staged in smem; each warp serves
// 4 batches (2 per half-warp, two v-registers) so every LDS.128 of P is
// amortized over 4 dot-product chains — halves the smem-crossbar cost per
// batch, which R3 ncu showed to be the binding resource (L1=77%).

#define NSITE 783
#define NPAIR 392
#define CHUNK 14             // pairs per chunk
#define NCHUNK 28            // 392 / 14
#define BPB 16               // batches per block (4 warps x 4)
#define THREADS 128
#define NBLOCK 128           // 128 * 16 = 2048 exactly
#define XV 8                 // float4 x-vectors staged per batch per chunk

__device__ float4 g_pmat[NPAIR * 100];

__device__ __forceinline__ void cpasync16(void* dst_smem, const void* src) {
    uint32_t d = (uint32_t)__cvta_generic_to_shared(dst_smem);
    asm volatile("cp.async.cg.shared.global [%0], [%1], 16;" :: "r"(d), "l"(src) : "memory");
}

// ---------------------------------------------------------------------------
// Precompute pair matrices. One block per pair, 128 threads (100 active).
// cores_mid layout: [n][l][f][h] -> ((l*2+f)*10 + h), n in [0,783)
// ---------------------------------------------------------------------------
__global__ void prep_pairs_kernel(const float* __restrict__ cm) {
    __shared__ float s1[200];
    __shared__ float s2[200];
    int j = blockIdx.x;
    int t = threadIdx.x;
    int s2i = 2 * j + 1;
    if (t < 100) {
        const float* p1 = cm + (2 * j) * 200;
        s1[t]       = p1[t];
        s1[t + 100] = p1[t + 100];
        if (s2i < NSITE) {
            const float* p2 = cm + s2i * 200;
            s2[t]       = p2[t];
            s2[t + 100] = p2[t + 100];
        } else {
            #pragma unroll
            for (int q = t; q < 200; q += 100) {
                int l = q / 20;
                int h = q % 10;
                s2[q] = (l == h) ? 1.0f : 0.0f;   // identity pad (D2 = 0)
            }
        }
    }
    __syncthreads();
    if (t >= 100) return;
    int l = t / 10;
    int h = t % 10;
    float p00 = 0.f, p10 = 0.f, p01 = 0.f, p11 = 0.f;
    #pragma unroll
    for (int k = 0; k < 10; k++) {
        float a1 = s1[l * 20 + k];
        float d1 = s1[l * 20 + 10 + k] - a1;
        float a2 = s2[k * 20 + h];
        float d2 = s2[k * 20 + 10 + h] - a2;
        p00 = fmaf(a1, a2, p00);
        p10 = fmaf(d1, a2, p10);
        p01 = fmaf(a1, d2, p01);
        p11 = fmaf(d1, d2, p11);
    }
    g_pmat[j * 100 + t] = make_float4(p00, p10, p01, p11);
}

// ---------------------------------------------------------------------------
// Main chain kernel. 128 threads = 4 warps = 16 batches.
// Warp w serves batches base+4w .. base+4w+3:
//   half 0 (lanes 0-15):  va = batch 4w+0, vb = batch 4w+1
//   half 1 (lanes 16-31): va = batch 4w+2, vb = batch 4w+3
// Lane h (h<10) owns component h; lanes 10-15 mirror lane 9.
// ---------------------------------------------------------------------------
__global__ void __launch_bounds__(THREADS, 1) mps_chain_kernel(
    const float* __restrict__ x,      // [2048, 784]
    const float* __restrict__ core0,  // [1, 2, 10]
    const float* __restrict__ cls,    // [10, 10]
    float* __restrict__ out)          // [2048, 10]
{
    __shared__ float4 bufP[2][CHUNK * 100];   // 2 x 22.4 KB
    __shared__ float4 bufX[2][BPB * XV];      // 2 x 2 KB (32 floats/batch)

    const unsigned FULL = 0xffffffffu;
    int tid  = threadIdx.x;
    int lane = tid & 31;
    int warp = tid >> 5;              // 0..3
    int half = lane >> 4;
    int h    = lane & 15;
    int hc   = (h < 10) ? h : 9;
    bool act = (h < 10);

    int base = blockIdx.x * BPB;
    int ia   = warp * 4 + half * 2;   // local batch index of va
    int ba   = base + ia;             // global batch of va
    int bb   = ba + 1;                // global batch of vb

    // chunk loader: 1400 pmat float4 + 16*XV x-float4
    auto issue_chunk = [&](int c) {
        int pb = c & 1;
        int nvec = (c == NCHUNK - 1) ? 7 : XV;   // last chunk: 756+28 = 784 (row end)
        const float4* psrc = g_pmat + c * (CHUNK * 100);
        for (int i = tid; i < CHUNK * 100 + BPB * XV; i += THREADS) {
            if (i < CHUNK * 100) {
                cpasync16(&bufP[pb][i], psrc + i);
            } else {
                int q  = i - CHUNK * 100;
                int bi = q >> 3, vv = q & 7;
                if (vv < nvec) {
                    cpasync16(&bufX[pb][bi * XV + vv],
                              x + (size_t)(base + bi) * 784 + c * (2 * CHUNK) + vv * 4);
                }
            }
        }
        asm volatile("cp.async.commit_group;" ::: "memory");
    };

    // heads
    float t0a = __ldg(x + (size_t)ba * 784);
    float t0b = __ldg(x + (size_t)bb * 784);
    float c0a = __ldg(core0 + hc);
    float c0d = __ldg(core0 + 10 + hc) - c0a;
    float va = fmaf(t0a, c0d, c0a);
    float vb = fmaf(t0b, c0d, c0a);
    int Ka = 0, Kb = 0;

    issue_chunk(0);
    asm volatile("cp.async.wait_group 0;" ::: "memory");
    __syncthreads();

    for (int c = 0; c < NCHUNK; c++) {
        int pb = c & 1;
        if (c + 1 < NCHUNK) issue_chunk(c + 1);

        const float4* P   = bufP[pb];
        const float*  txa = (const float*)(&bufX[pb][ia * XV]);
        const float*  txb = (const float*)(&bufX[pb][(ia + 1) * XV]);

        #pragma unroll 2
        for (int jj = 0; jj < CHUNK; jj++) {
            // identity-padded pair (last of last chunk): t2 reads a stale but
            // finite slot; it multiplies p01 = p11 = 0.
            float t1a = txa[2 * jj + 1], t2a = txa[2 * jj + 2];
            float t1b = txb[2 * jj + 1], t2b = txb[2 * jj + 2];
            float ca = t1a * t2a;
            float cb = t1b * t2b;
            const float4* p = P + jj * 100 + hc;
            float wa0 = 0.f, wa1 = 0.f, wb0 = 0.f, wb1 = 0.f;
            #pragma unroll
            for (int l = 0; l < 10; l += 2) {
                float vla0 = __shfl_sync(FULL, va, l, 16);
                float vla1 = __shfl_sync(FULL, va, l + 1, 16);
                float vlb0 = __shfl_sync(FULL, vb, l, 16);
                float vlb1 = __shfl_sync(FULL, vb, l + 1, 16);
                float4 r0 = p[l * 10];
                float4 r1 = p[(l + 1) * 10];
                float ma0 = fmaf(t1a, r0.y, r0.x); ma0 = fmaf(t2a, r0.z, ma0); ma0 = fmaf(ca, r0.w, ma0);
                float mb0 = fmaf(t1b, r0.y, r0.x); mb0 = fmaf(t2b, r0.z, mb0); mb0 = fmaf(cb, r0.w, mb0);
                wa0 = fmaf(vla0, ma0, wa0);
                wb0 = fmaf(vlb0, mb0, wb0);
                float ma1 = fmaf(t1a, r1.y, r1.x); ma1 = fmaf(t2a, r1.z, ma1); ma1 = fmaf(ca, r1.w, ma1);
                float mb1 = fmaf(t1b, r1.y, r1.x); mb1 = fmaf(t2b, r1.z, mb1); mb1 = fmaf(cb, r1.w, mb1);
                wa1 = fmaf(vla1, ma1, wa1);
                wb1 = fmaf(vlb1, mb1, wb1);
            }
            va = wa0 + wa1;
            vb = wb0 + wb1;
        }

        // exact power-of-2 rescale per batch (no sqrt/log on the hot path)
        {
            float ssa = act ? va * va : 0.0f;
            float ssb = act ? vb * vb : 0.0f;
            ssa += __shfl_xor_sync(FULL, ssa, 1, 16);
            ssb += __shfl_xor_sync(FULL, ssb, 1, 16);
            ssa += __shfl_xor_sync(FULL, ssa, 2, 16);
            ssb += __shfl_xor_sync(FULL, ssb, 2, 16);
            ssa += __shfl_xor_sync(FULL, ssa, 4, 16);
            ssb += __shfl_xor_sync(FULL, ssb, 4, 16);
            ssa += __shfl_xor_sync(FULL, ssa, 8, 16);
            ssb += __shfl_xor_sync(FULL, ssb, 8, 16);
            int sha = (((__float_as_int(ssa) >> 23) & 0xff) - 127) >> 1;
            int shb = (((__float_as_int(ssb) >> 23) & 0xff) - 127) >> 1;
            Ka += sha;
            Kb += shb;
            va *= __int_as_float((127 - sha) << 23);
            vb *= __int_as_float((127 - shb) << 23);
        }

        if (c + 1 < NCHUNK)
            asm volatile("cp.async.wait_group 0;" ::: "memory");
        __syncthreads();
    }

    // final norm + single log per batch
    float ssa = act ? va * va : 0.0f;
    float ssb = act ? vb * vb : 0.0f;
    ssa += __shfl_xor_sync(FULL, ssa, 1, 16);
    ssb += __shfl_xor_sync(FULL, ssb, 1, 16);
    ssa += __shfl_xor_sync(FULL, ssa, 2, 16);
    ssb += __shfl_xor_sync(FULL, ssb, 2, 16);
    ssa += __shfl_xor_sync(FULL, ssa, 4, 16);
    ssb += __shfl_xor_sync(FULL, ssb, 4, 16);
    ssa += __shfl_xor_sync(FULL, ssa, 8, 16);
    ssb += __shfl_xor_sync(FULL, ssb, 8, 16);
    float na = fmaxf(sqrtf(ssa), 1e-30f);
    float nb = fmaxf(sqrtf(ssb), 1e-30f);
    const float LN2 = 0.69314718055994531f;
    float lna = (float)Ka * LN2 + __logf(na);
    float lnb = (float)Kb * LN2 + __logf(nb);
    va *= (1.0f / na);
    vb *= (1.0f / nb);

    // logits[b,o] = sum_l v_l * cls[o,l] + lognorm   (lane h = class o)
    float cw[10];
    #pragma unroll
    for (int l = 0; l < 10; l++) cw[l] = __ldg(cls + hc * 10 + l);
    float acca = lna, accb = lnb;
    #pragma unroll
    for (int l = 0; l < 10; l++) {
        float vla = __shfl_sync(FULL, va, l, 16);
        float vlb = __shfl_sync(FULL, vb, l, 16);
        acca = fmaf(vla, cw[l], acca);
        accb = fmaf(vlb, cw[l], accb);
    }
    if (act) {
        out[(size_t)ba * 10 + h] = acca;
        out[(size_t)bb * 10 + h] = accb;
    }
}

// ---------------------------------------------------------------------------
extern "C" void kernel_launch(void* const* d_in, const int* in_sizes, int n_in,
                              void* d_out, int out_size) {
    const float* x     = (const float*)d_in[0];  // [2048, 784]
    const float* core0 = (const float*)d_in[1];  // [1, 2, 10]
    const float* cm    = (const float*)d_in[2];  // [783, 10, 2, 10]
    const float* cls   = (const float*)d_in[3];  // [10, 10]
    float* out = (float*)d_out;                  // [2048, 10]

    prep_pairs_kernel<<<NPAIR, 128>>>(cm);
    mps_chain_kernel<<<NBLOCK, THREADS>>>(x, core0, cls, out);
}

// round 5
// speedup vs baseline: 1.5036x; 1.0101x over previous
#include <cuda_runtime.h>
#include <cstdint>

// MPS classifier: logits[b] = unit(v_b @ prod_n M_n(b)) @ C^T + log||prod||
// Pair-fused matrices P (batch-independent) staged in smem; each warp serves
// 4 batches (2 per half-warp). R5: latency-batched step body — all LDS.128
// and all SHFLs for a step issue up front (m-build is v-independent), so the
// single warp per SMSP can cover LDS/SHFL latency with its own m-build FMAs.

#define NSITE 783
#define NPAIR 392
#define CHUNK 14             // pairs per chunk
#define NCHUNK 28            // 392 / 14
#define BPB 16               // batches per block (4 warps x 4)
#define THREADS 128
#define NBLOCK 128           // 128 * 16 = 2048 exactly
#define XV 8                 // float4 x-vectors staged per batch per chunk

__device__ float4 g_pmat[NPAIR * 100];

__device__ __forceinline__ void cpasync16(void* dst_smem, const void* src) {
    uint32_t d = (uint32_t)__cvta_generic_to_shared(dst_smem);
    asm volatile("cp.async.cg.shared.global [%0], [%1], 16;" :: "r"(d), "l"(src) : "memory");
}

// ---------------------------------------------------------------------------
// Precompute pair matrices. One block per pair, 128 threads (100 active).
// cores_mid layout: [n][l][f][h] -> ((l*2+f)*10 + h), n in [0,783)
// ---------------------------------------------------------------------------
__global__ void prep_pairs_kernel(const float* __restrict__ cm) {
    __shared__ float s1[200];
    __shared__ float s2[200];
    int j = blockIdx.x;
    int t = threadIdx.x;
    int s2i = 2 * j + 1;
    if (t < 100) {
        const float* p1 = cm + (2 * j) * 200;
        s1[t]       = p1[t];
        s1[t + 100] = p1[t + 100];
        if (s2i < NSITE) {
            const float* p2 = cm + s2i * 200;
            s2[t]       = p2[t];
            s2[t + 100] = p2[t + 100];
        } else {
            #pragma unroll
            for (int q = t; q < 200; q += 100) {
                int l = q / 20;
                int h = q % 10;
                s2[q] = (l == h) ? 1.0f : 0.0f;   // identity pad (D2 = 0)
            }
        }
    }
    __syncthreads();
    if (t >= 100) return;
    int l = t / 10;
    int h = t % 10;
    float p00 = 0.f, p10 = 0.f, p01 = 0.f, p11 = 0.f;
    #pragma unroll
    for (int k = 0; k < 10; k++) {
        float a1 = s1[l * 20 + k];
        float d1 = s1[l * 20 + 10 + k] - a1;
        float a2 = s2[k * 20 + h];
        float d2 = s2[k * 20 + 10 + h] - a2;
        p00 = fmaf(a1, a2, p00);
        p10 = fmaf(d1, a2, p10);
        p01 = fmaf(a1, d2, p01);
        p11 = fmaf(d1, d2, p11);
    }
    g_pmat[j * 100 + t] = make_float4(p00, p10, p01, p11);
}

// ---------------------------------------------------------------------------
// Main chain kernel. 128 threads = 4 warps = 16 batches (1 warp per SMSP).
// Warp w serves batches base+4w .. base+4w+3:
//   half 0 (lanes 0-15):  va = batch 4w+0, vb = batch 4w+1
//   half 1 (lanes 16-31): va = batch 4w+2, vb = batch 4w+3
// Lane h (h<10) owns component h; lanes 10-15 mirror lane 9.
// ---------------------------------------------------------------------------
__global__ void __launch_bounds__(THREADS, 1) mps_chain_kernel(
    const float* __restrict__ x,      // [2048, 784]
    const float* __restrict__ core0,  // [1, 2, 10]
    const float* __restrict__ cls,    // [10, 10]
    float* __restrict__ out)          // [2048, 10]
{
    __shared__ float4 bufP[2][CHUNK * 100];   // 2 x 22.4 KB
    __shared__ float4 bufX[2][BPB * XV];      // 2 x 2 KB (32 floats/batch)

    const unsigned FULL = 0xffffffffu;
    int tid  = threadIdx.x;
    int lane = tid & 31;
    int warp = tid >> 5;              // 0..3
    int half = lane >> 4;
    int h    = lane & 15;
    int hc   = (h < 10) ? h : 9;
    bool act = (h < 10);

    int base = blockIdx.x * BPB;
    int ia   = warp * 4 + half * 2;   // local batch index of va
    int ba   = base + ia;             // global batch of va
    int bb   = ba + 1;                // global batch of vb

    // chunk loader: 1400 pmat float4 + 16*XV x-float4
    auto issue_chunk = [&](int c) {
        int pb = c & 1;
        int nvec = (c == NCHUNK - 1) ? 7 : XV;   // last chunk: 756+28 = 784 (row end)
        const float4* psrc = g_pmat + c * (CHUNK * 100);
        for (int i = tid; i < CHUNK * 100 + BPB * XV; i += THREADS) {
            if (i < CHUNK * 100) {
                cpasync16(&bufP[pb][i], psrc + i);
            } else {
                int q  = i - CHUNK * 100;
                int bi = q >> 3, vv = q & 7;
                if (vv < nvec) {
                    cpasync16(&bufX[pb][bi * XV + vv],
                              x + (size_t)(base + bi) * 784 + c * (2 * CHUNK) + vv * 4);
                }
            }
        }
        asm volatile("cp.async.commit_group;" ::: "memory");
    };

    // heads
    float t0a = __ldg(x + (size_t)ba * 784);
    float t0b = __ldg(x + (size_t)bb * 784);
    float c0a = __ldg(core0 + hc);
    float c0d = __ldg(core0 + 10 + hc) - c0a;
    float va = fmaf(t0a, c0d, c0a);
    float vb = fmaf(t0b, c0d, c0a);
    int Ka = 0, Kb = 0;

    issue_chunk(0);
    asm volatile("cp.async.wait_group 0;" ::: "memory");
    __syncthreads();

    for (int c = 0; c < NCHUNK; c++) {
        int pb = c & 1;
        if (c + 1 < NCHUNK) issue_chunk(c + 1);

        const float4* P   = bufP[pb];
        const float*  txa = (const float*)(&bufX[pb][ia * XV]);
        const float*  txb = (const float*)(&bufX[pb][(ia + 1) * XV]);

        #pragma unroll 2
        for (int jj = 0; jj < CHUNK; jj++) {
            // identity-padded pair (last of last chunk): t2 reads a stale but
            // finite slot; it multiplies p01 = p11 = 0.
            float t1a = txa[2 * jj + 1], t2a = txa[2 * jj + 2];
            float t1b = txb[2 * jj + 1], t2b = txb[2 * jj + 2];
            float ca = t1a * t2a;
            float cb = t1b * t2b;
            const float4* p = P + jj * 100 + hc;

            // ---- phase 1: issue all loads (long-latency, pipelined) ----
            float4 r[10];
            #pragma unroll
            for (int l = 0; l < 10; l++) r[l] = p[l * 10];

            // ---- phase 2: issue all shuffles (independent of loads) ----
            float vla[10], vlb[10];
            #pragma unroll
            for (int l = 0; l < 10; l++) {
                vla[l] = __shfl_sync(FULL, va, l, 16);
                vlb[l] = __shfl_sync(FULL, vb, l, 16);
            }

            // ---- phase 3: m-build + accumulate ----
            float wa0 = 0.f, wa1 = 0.f, wb0 = 0.f, wb1 = 0.f;
            #pragma unroll
            for (int l = 0; l < 10; l += 2) {
                float4 r0 = r[l];
                float4 r1 = r[l + 1];
                float ma0 = fmaf(t1a, r0.y, r0.x); ma0 = fmaf(t2a, r0.z, ma0); ma0 = fmaf(ca, r0.w, ma0);
                float mb0 = fmaf(t1b, r0.y, r0.x); mb0 = fmaf(t2b, r0.z, mb0); mb0 = fmaf(cb, r0.w, mb0);
                float ma1 = fmaf(t1a, r1.y, r1.x); ma1 = fmaf(t2a, r1.z, ma1); ma1 = fmaf(ca, r1.w, ma1);
                float mb1 = fmaf(t1b, r1.y, r1.x); mb1 = fmaf(t2b, r1.z, mb1); mb1 = fmaf(cb, r1.w, mb1);
                wa0 = fmaf(vla[l],     ma0, wa0);
                wb0 = fmaf(vlb[l],     mb0, wb0);
                wa1 = fmaf(vla[l + 1], ma1, wa1);
                wb1 = fmaf(vlb[l + 1], mb1, wb1);
            }
            va = wa0 + wa1;
            vb = wb0 + wb1;
        }

        // exact power-of-2 rescale per batch (no sqrt/log on the hot path)
        {
            float ssa = act ? va * va : 0.0f;
            float ssb = act ? vb * vb : 0.0f;
            ssa += __shfl_xor_sync(FULL, ssa, 1, 16);
            ssb += __shfl_xor_sync(FULL, ssb, 1, 16);
            ssa += __shfl_xor_sync(FULL, ssa, 2, 16);
            ssb += __shfl_xor_sync(FULL, ssb, 2, 16);
            ssa += __shfl_xor_sync(FULL, ssa, 4, 16);
            ssb += __shfl_xor_sync(FULL, ssb, 4, 16);
            ssa += __shfl_xor_sync(FULL, ssa, 8, 16);
            ssb += __shfl_xor_sync(FULL, ssb, 8, 16);
            int sha = (((__float_as_int(ssa) >> 23) & 0xff) - 127) >> 1;
            int shb = (((__float_as_int(ssb) >> 23) & 0xff) - 127) >> 1;
            Ka += sha;
            Kb += shb;
            va *= __int_as_float((127 - sha) << 23);
            vb *= __int_as_float((127 - shb) << 23);
        }

        if (c + 1 < NCHUNK)
            asm volatile("cp.async.wait_group 0;" ::: "memory");
        __syncthreads();
    }

    // final norm + single log per batch
    float ssa = act ? va * va : 0.0f;
    float ssb = act ? vb * vb : 0.0f;
    ssa += __shfl_xor_sync(FULL, ssa, 1, 16);
    ssb += __shfl_xor_sync(FULL, ssb, 1, 16);
    ssa += __shfl_xor_sync(FULL, ssa, 2, 16);
    ssb += __shfl_xor_sync(FULL, ssb, 2, 16);
    ssa += __shfl_xor_sync(FULL, ssa, 4, 16);
    ssb += __shfl_xor_sync(FULL, ssb, 4, 16);
    ssa += __shfl_xor_sync(FULL, ssa, 8, 16);
    ssb += __shfl_xor_sync(FULL, ssb, 8, 16);
    float na = fmaxf(sqrtf(ssa), 1e-30f);
    float nb = fmaxf(sqrtf(ssb), 1e-30f);
    const float LN2 = 0.69314718055994531f;
    float lna = (float)Ka * LN2 + __logf(na);
    float lnb = (float)Kb * LN2 + __logf(nb);
    va *= (1.0f / na);
    vb *= (1.0f / nb);

    // logits[b,o] = sum_l v_l * cls[o,l] + lognorm   (lane h = class o)
    float cw[10];
    #pragma unroll
    for (int l = 0; l < 10; l++) cw[l] = __ldg(cls + hc * 10 + l);
    float acca = lna, accb = lnb;
    #pragma unroll
    for (int l = 0; l < 10; l++) {
        float vla = __shfl_sync(FULL, va, l, 16);
        float vlb = __shfl_sync(FULL, vb, l, 16);
        acca = fmaf(vla, cw[l], acca);
        accb = fmaf(vlb, cw[l], accb);
    }
    if (act) {
        out[(size_t)ba * 10 + h] = acca;
        out[(size_t)bb * 10 + h] = accb;
    }
}

// ---------------------------------------------------------------------------
extern "C" void kernel_launch(void* const* d_in, const int* in_sizes, int n_in,
                              void* d_out, int out_size) {
    const float* x     = (const float*)d_in[0];  // [2048, 784]
    const float* core0 = (const float*)d_in[1];  // [1, 2, 10]
    const float* cm    = (const float*)d_in[2];  // [783, 10, 2, 10]
    const float* cls   = (const float*)d_in[3];  // [10, 10]
    float* out = (float*)d_out;                  // [2048, 10]

    prep_pairs_kernel<<<NPAIR, 128>>>(cm);
    mps_chain_kernel<<<NBLOCK, THREADS>>>(x, core0, cls, out);
}